// round 14
// baseline (speedup 1.0000x reference)
#include <cuda_runtime.h>
#include <cuda_bf16.h>
#include <math.h>
#include <stdint.h>

#define B_   32
#define C_   192
#define HH   56
#define WW   56
#define HW   3136
#define CO   384
#define K2   384
#define BN_EPS 1e-5f

// A' [32*3136][384] fp32 (tf32-rounded): cols 0..191 = x, 192..383 = xj
__device__ float g_at[(size_t)B_ * HW * K2];
__device__ float g_wt[CO * K2];          // tf32-rounded weights [o][k]
__device__ float g_cmin[B_ * C_ * 112];  // [bc][par*56+q]
__device__ float g_rmin[B_ * C_ * 112];  // [bc][p*2+par]

__device__ __forceinline__ uint32_t tf32r(float f) {
    uint32_t t; asm("cvt.rna.tf32.f32 %0, %1;" : "=r"(t) : "f"(f)); return t;
}

// ===================== passA: parity mins per (b,c) =====================
__global__ __launch_bounds__(256) void passA_kernel(const float* __restrict__ x) {
    __shared__ float img[HW];
    const int bc = blockIdx.x;
    const float* xp = x + (size_t)bc * HW;
    for (int i = threadIdx.x; i < HW; i += 256) img[i] = xp[i];
    __syncthreads();
    int t = threadIdx.x;
    if (t < 112) {
        int par = t / 56, q = t % 56;
        float m = 3.4e38f;
        #pragma unroll 7
        for (int r = par; r < HH; r += 2) m = fminf(m, img[r * WW + q]);
        g_cmin[bc * 112 + t] = m;
    } else if (t < 224) {
        int t2 = t - 112;
        int par = t2 / 56, p = t2 % 56;
        float m = 3.4e38f;
        const float* row = &img[p * WW];
        #pragma unroll 7
        for (int q = par; q < WW; q += 2) m = fminf(m, row[q]);
        g_rmin[bc * 112 + p * 2 + par] = m;
    }
}

// ===================== passB: xj + transpose to A'[g][384] (tf32) =====================
__global__ __launch_bounds__(256) void passB_kernel(const float* __restrict__ x) {
    extern __shared__ float st[];
    const int b = blockIdx.y, p0 = blockIdx.x * 32;
    const int wid = threadIdx.x >> 5, lane = threadIdx.x & 31;
    const int gp = p0 + lane;
    const int pp = gp / WW, qq = gp - pp * WW;
    const int cbase = (pp & 1) * 56 + qq;
    const int rbase = pp * 2 + (qq & 1);
    for (int c = wid; c < C_; c += 8) {
        int bc = b * C_ + c;
        float v  = x[(size_t)bc * HW + gp];
        float cm = g_cmin[bc * 112 + cbase];
        float rm = g_rmin[bc * 112 + rbase];
        float xj = v - fminf(cm, rm);
        st[lane * 385 + c] = v;
        st[lane * 385 + C_ + c] = xj;
    }
    __syncthreads();
    uint4* dst = (uint4*)(g_at + ((size_t)b * HW + p0) * K2);
    for (int i = threadIdx.x; i < 32 * 96; i += 256) {
        int px = i / 96, c4 = (i - px * 96) * 4;
        const float* s = &st[px * 385 + c4];
        uint4 v;
        v.x = tf32r(s[0]); v.y = tf32r(s[1]);
        v.z = tf32r(s[2]); v.w = tf32r(s[3]);
        dst[px * 96 + (c4 >> 2)] = v;
    }
}

__global__ __launch_bounds__(256) void wconv_kernel(const float* __restrict__ Wc) {
    int idx = blockIdx.x * 256 + threadIdx.x;
    if (idx < CO * K2) ((uint32_t*)g_wt)[idx] = tf32r(Wc[idx]);
}

// ===================== GEMM: tf32 m16n8k8, 6-stage, frag double-buffer =====================
// Stage: A [128m][144B] = 18432, B [128n][144B] = 18432
#define OFF_B  18432
#define BUFSZ  36864
#define STAGES 6
#define OFF_SC (STAGES * BUFSZ)
#define OFF_SH (OFF_SC + 512)
#define SMEM_TOTAL (OFF_SH + 512)

__device__ __forceinline__ uint32_t smem_u32(const void* p) {
    uint32_t a;
    asm("{ .reg .u64 t; cvta.to.shared.u64 t, %1; cvt.u32.u64 %0, t; }" : "=r"(a) : "l"(p));
    return a;
}
__device__ __forceinline__ void cp16(uint32_t dst, const void* src) {
    asm volatile("cp.async.cg.shared.global [%0], [%1], 16;" :: "r"(dst), "l"(src));
}
#define CP_COMMIT() asm volatile("cp.async.commit_group;" ::: "memory")
#define CP_WAIT2()  asm volatile("cp.async.wait_group 2;" ::: "memory")

__device__ __forceinline__ void ldsm_x4(uint32_t* r, uint32_t a) {
    asm volatile("ldmatrix.sync.aligned.m8n8.x4.shared.b16 {%0,%1,%2,%3}, [%4];"
        : "=r"(r[0]), "=r"(r[1]), "=r"(r[2]), "=r"(r[3]) : "r"(a));
}
__device__ __forceinline__ void mma_tf32(float* c, const uint32_t* a, const uint32_t* b) {
    asm volatile("mma.sync.aligned.m16n8k8.row.col.f32.tf32.tf32.f32 "
        "{%0,%1,%2,%3},{%4,%5,%6,%7},{%8,%9},{%0,%1,%2,%3};"
        : "+f"(c[0]), "+f"(c[1]), "+f"(c[2]), "+f"(c[3])
        : "r"(a[0]), "r"(a[1]), "r"(a[2]), "r"(a[3]), "r"(b[0]), "r"(b[1]));
}

__global__ __launch_bounds__(512, 1) void gemm_tf32_kernel(
    const float* __restrict__ bconv, const float* __restrict__ gamma,
    const float* __restrict__ beta,  const float* __restrict__ rmean,
    const float* __restrict__ rvar,  float* __restrict__ out)
{
    extern __shared__ char sm[];
    const uint32_t sbase = smem_u32(sm);
    const int tid = threadIdx.x, wid = tid >> 5, lid = tid & 31;
    const int o0 = blockIdx.x * 128;
    const int g0 = blockIdx.y * 128;
    const int warp_m = wid >> 2, warp_n = wid & 3;   // 4x4 warps, 32x32 tiles

    float* scp = (float*)(sm + OFF_SC);
    float* shp = (float*)(sm + OFF_SH);
    if (tid < 128) {
        int o = o0 + tid;
        float sc = gamma[o] * rsqrtf(rvar[o] + BN_EPS);
        scp[tid] = sc;
        shp[tid] = (bconv[o] - rmean[o]) * sc + beta[o];
    }

    // ---- loaders: per thread 2x16B per operand per stage ----
    const int am0 = (tid * 2) >> 3;
    const int akc = (tid * 2) & 7;
    const float* asrc = g_at + (size_t)(g0 + am0) * K2 + akc * 4;
    const uint32_t adst = (uint32_t)(am0 * 144 + akc * 16);
    const float* bsrc = g_wt + (size_t)(o0 + am0) * K2 + akc * 4;
    const uint32_t bdst = (uint32_t)(OFF_B + am0 * 144 + akc * 16);

    auto produce = [&](int ci, uint32_t buf) {
        #pragma unroll
        for (int j = 0; j < 2; j++) {
            cp16(buf + adst + j * 16u, asrc + ci * 32 + j * 4);
            cp16(buf + bdst + j * 16u, bsrc + ci * 32 + j * 4);
        }
    };

    float acc[2][4][4];
    #pragma unroll
    for (int i = 0; i < 2; i++)
        #pragma unroll
        for (int j = 0; j < 4; j++)
            #pragma unroll
            for (int e = 0; e < 4; e++) acc[i][j][e] = 0.f;

    const uint32_t a_off = (uint32_t)((warp_m * 32 + (lid & 15)) * 144 + (lid & 16));
    const uint32_t b_off = (uint32_t)(OFF_B +
        (warp_n * 32 + (lid & 7) + ((lid & 16) >> 1)) * 144 + ((lid & 8) << 1));

    // prologue: chunks 0..3 -> stages 0..3
    #pragma unroll
    for (int s = 0; s < 4; s++) {
        produce(s, sbase + (uint32_t)s * BUFSZ);
        CP_COMMIT();
    }

    uint32_t af[2][2][4], bf[2][2][4];
    int st0 = 0;
    for (int p = 0; p < 6; p++) {           // 2 chunks per iteration
        CP_WAIT2();
        __syncthreads();
        if (p < 4) {
            int c4 = 2 * p + 4;
            int s4 = st0 + 4; if (s4 >= 6) s4 -= 6;
            produce(c4,     sbase + (uint32_t)s4 * BUFSZ);       CP_COMMIT();
            produce(c4 + 1, sbase + (uint32_t)(s4 + 1) * BUFSZ); CP_COMMIT();
        } else {
            CP_COMMIT();                    // empty groups keep wait-count honest
            CP_COMMIT();
        }

        const uint32_t buf0 = sbase + (uint32_t)st0 * BUFSZ;
        const uint32_t buf1 = buf0 + BUFSZ;

        // frag-prefetch helper: step s in 0..7 (chunk = s>>2, k-step = s&3)
        #define LDFRAGS(s_, pb_) do { \
            uint32_t _b = ((s_) < 4) ? buf0 : buf1; \
            uint32_t _k = (uint32_t)((s_) & 3) * 32u; \
            ldsm_x4(af[pb_][0], _b + a_off + _k); \
            ldsm_x4(af[pb_][1], _b + a_off + 16u * 144u + _k); \
            ldsm_x4(bf[pb_][0], _b + b_off + _k); \
            ldsm_x4(bf[pb_][1], _b + b_off + 16u * 144u + _k); \
        } while (0)

        LDFRAGS(0, 0);
        #pragma unroll
        for (int s = 0; s < 8; s++) {
            const int cur = s & 1, nxt = cur ^ 1;
            if (s < 7) LDFRAGS(s + 1, nxt);
            #pragma unroll
            for (int mf = 0; mf < 2; mf++)
                #pragma unroll
                for (int nf = 0; nf < 4; nf++)
                    mma_tf32(acc[mf][nf], af[cur][mf], &bf[cur][nf >> 1][(nf & 1) * 2]);
        }
        #undef LDFRAGS

        st0 += 2; if (st0 >= 6) st0 -= 6;
    }

    // ---- epilogue: BN + exact GELU ----
    #pragma unroll
    for (int mf = 0; mf < 2; mf++) {
        const int ml = warp_m * 32 + mf * 16 + (lid >> 2);
        #pragma unroll
        for (int half = 0; half < 2; half++) {
            int g = g0 + ml + half * 8;
            int bb = g / HW, p = g - bb * HW;
            float* orow = out + ((size_t)bb * CO + o0) * HW + p;
            #pragma unroll
            for (int nf = 0; nf < 4; nf++) {
                #pragma unroll
                for (int e = 0; e < 2; e++) {
                    int n = warp_n * 32 + nf * 8 + (lid & 3) * 2 + e;
                    float y = acc[mf][nf][half * 2 + e] * scp[n] + shp[n];
                    y = 0.5f * y * (1.0f + erff(y * 0.70710678118654752f));
                    orow[(size_t)n * HW] = y;
                }
            }
        }
    }
}

extern "C" void kernel_launch(void* const* d_in, const int* in_sizes, int n_in,
                              void* d_out, int out_size) {
    const float* x     = (const float*)d_in[0];
    const float* Wc    = (const float*)d_in[1];
    const float* bconv = (const float*)d_in[2];
    const float* gamma = (const float*)d_in[3];
    const float* beta  = (const float*)d_in[4];
    const float* rmean = (const float*)d_in[5];
    const float* rvar  = (const float*)d_in[6];
    float* out = (float*)d_out;

    passA_kernel<<<B_ * C_, 256>>>(x);
    cudaFuncSetAttribute(passB_kernel,
                         cudaFuncAttributeMaxDynamicSharedMemorySize, 32 * 385 * 4);
    dim3 gB(HW / 32, B_);   // (98, 32)
    passB_kernel<<<gB, 256, 32 * 385 * 4>>>(x);
    wconv_kernel<<<(CO * K2 + 255) / 256, 256>>>(Wc);

    cudaFuncSetAttribute(gemm_tf32_kernel,
                         cudaFuncAttributeMaxDynamicSharedMemorySize, SMEM_TOTAL);
    dim3 grid(CO / 128, HW * B_ / 128);   // (3, 784)
    gemm_tf32_kernel<<<grid, 512, SMEM_TOTAL>>>(bconv, gamma, beta, rmean, rvar, out);
}

// round 16
// speedup vs baseline: 1.0336x; 1.0336x over previous
#include <cuda_runtime.h>
#include <cuda_bf16.h>
#include <math.h>
#include <stdint.h>

#define B_   32
#define C_   192
#define HH   56
#define WW   56
#define HW   3136
#define CO   384
#define K2   384
#define BN_EPS 1e-5f

// A' [32*3136][384] fp32 (tf32-rounded): cols 0..191 = x, 192..383 = xj
__device__ float g_at[(size_t)B_ * HW * K2];
__device__ float g_wt[CO * K2];          // tf32-rounded weights [o][k]
__device__ float g_cmin[B_ * C_ * 112];  // [bc][par*56+q]
__device__ float g_rmin[B_ * C_ * 112];  // [bc][p*2+par]

__device__ __forceinline__ uint32_t tf32r(float f) {
    uint32_t t; asm("cvt.rna.tf32.f32 %0, %1;" : "=r"(t) : "f"(f)); return t;
}

// ===================== passA: parity mins per (b,c) =====================
__global__ __launch_bounds__(256) void passA_kernel(const float* __restrict__ x) {
    __shared__ float img[HW];
    const int bc = blockIdx.x;
    const float* xp = x + (size_t)bc * HW;
    for (int i = threadIdx.x; i < HW; i += 256) img[i] = xp[i];
    __syncthreads();
    int t = threadIdx.x;
    if (t < 112) {
        int par = t / 56, q = t % 56;
        float m = 3.4e38f;
        #pragma unroll 7
        for (int r = par; r < HH; r += 2) m = fminf(m, img[r * WW + q]);
        g_cmin[bc * 112 + t] = m;
    } else if (t < 224) {
        int t2 = t - 112;
        int par = t2 / 56, p = t2 % 56;
        float m = 3.4e38f;
        const float* row = &img[p * WW];
        #pragma unroll 7
        for (int q = par; q < WW; q += 2) m = fminf(m, row[q]);
        g_rmin[bc * 112 + p * 2 + par] = m;
    }
}

// ===================== passB: xj + transpose to A'[g][384] (tf32) =====================
__global__ __launch_bounds__(256) void passB_kernel(const float* __restrict__ x) {
    extern __shared__ float st[];
    const int b = blockIdx.y, p0 = blockIdx.x * 32;
    const int wid = threadIdx.x >> 5, lane = threadIdx.x & 31;
    const int gp = p0 + lane;
    const int pp = gp / WW, qq = gp - pp * WW;
    const int cbase = (pp & 1) * 56 + qq;
    const int rbase = pp * 2 + (qq & 1);
    for (int c = wid; c < C_; c += 8) {
        int bc = b * C_ + c;
        float v  = x[(size_t)bc * HW + gp];
        float cm = g_cmin[bc * 112 + cbase];
        float rm = g_rmin[bc * 112 + rbase];
        float xj = v - fminf(cm, rm);
        st[lane * 385 + c] = v;
        st[lane * 385 + C_ + c] = xj;
    }
    __syncthreads();
    uint4* dst = (uint4*)(g_at + ((size_t)b * HW + p0) * K2);
    for (int i = threadIdx.x; i < 32 * 96; i += 256) {
        int px = i / 96, c4 = (i - px * 96) * 4;
        const float* s = &st[px * 385 + c4];
        uint4 v;
        v.x = tf32r(s[0]); v.y = tf32r(s[1]);
        v.z = tf32r(s[2]); v.w = tf32r(s[3]);
        dst[px * 96 + (c4 >> 2)] = v;
    }
}

__global__ __launch_bounds__(256) void wconv_kernel(const float* __restrict__ Wc) {
    int idx = blockIdx.x * 256 + threadIdx.x;
    if (idx < CO * K2) ((uint32_t*)g_wt)[idx] = tf32r(Wc[idx]);
}

// ========== GEMM: tf32 m16n8k8, 8 warps x 64x32 tiles, 3-stage, 2 CTAs/SM ==========
// Stage: A [128m][144B] = 18432, B [128n][144B] = 18432
#define OFF_B  18432
#define BUFSZ  36864
#define STAGES 3
#define OFF_SC (STAGES * BUFSZ)
#define OFF_SH (OFF_SC + 512)
#define SMEM_TOTAL (OFF_SH + 512)

__device__ __forceinline__ uint32_t smem_u32(const void* p) {
    uint32_t a;
    asm("{ .reg .u64 t; cvta.to.shared.u64 t, %1; cvt.u32.u64 %0, t; }" : "=r"(a) : "l"(p));
    return a;
}
__device__ __forceinline__ void cp16(uint32_t dst, const void* src) {
    asm volatile("cp.async.cg.shared.global [%0], [%1], 16;" :: "r"(dst), "l"(src));
}
#define CP_COMMIT() asm volatile("cp.async.commit_group;" ::: "memory")
#define CP_WAIT1()  asm volatile("cp.async.wait_group 1;" ::: "memory")

__device__ __forceinline__ void ldsm_x4(uint32_t* r, uint32_t a) {
    asm volatile("ldmatrix.sync.aligned.m8n8.x4.shared.b16 {%0,%1,%2,%3}, [%4];"
        : "=r"(r[0]), "=r"(r[1]), "=r"(r[2]), "=r"(r[3]) : "r"(a));
}
__device__ __forceinline__ void mma_tf32(float* c, const uint32_t* a, const uint32_t* b) {
    asm volatile("mma.sync.aligned.m16n8k8.row.col.f32.tf32.tf32.f32 "
        "{%0,%1,%2,%3},{%4,%5,%6,%7},{%8,%9},{%0,%1,%2,%3};"
        : "+f"(c[0]), "+f"(c[1]), "+f"(c[2]), "+f"(c[3])
        : "r"(a[0]), "r"(a[1]), "r"(a[2]), "r"(a[3]), "r"(b[0]), "r"(b[1]));
}

__global__ __launch_bounds__(256, 2) void gemm_tf32_kernel(
    const float* __restrict__ bconv, const float* __restrict__ gamma,
    const float* __restrict__ beta,  const float* __restrict__ rmean,
    const float* __restrict__ rvar,  float* __restrict__ out)
{
    extern __shared__ char sm[];
    const uint32_t sbase = smem_u32(sm);
    const int tid = threadIdx.x, wid = tid >> 5, lid = tid & 31;
    const int o0 = blockIdx.x * 128;
    const int g0 = blockIdx.y * 128;
    const int warp_m = wid >> 2, warp_n = wid & 3;   // 2x4 warps, 64x32 tiles

    float* scp = (float*)(sm + OFF_SC);
    float* shp = (float*)(sm + OFF_SH);
    if (tid < 128) {
        int o = o0 + tid;
        float sc = gamma[o] * rsqrtf(rvar[o] + BN_EPS);
        scp[tid] = sc;
        shp[tid] = (bconv[o] - rmean[o]) * sc + beta[o];
    }

    // ---- loaders: 256 threads, per stage 4x16B A + 4x16B B each ----
    const int arow = tid >> 1;               // 0..127
    const int akc0 = (tid & 1) * 4;          // chunks akc0..akc0+3 (16B each)
    const float* asrc = g_at + (size_t)(g0 + arow) * K2 + akc0 * 4;
    const uint32_t adst = (uint32_t)(arow * 144 + akc0 * 16);
    const float* bsrc = g_wt + (size_t)(o0 + arow) * K2 + akc0 * 4;
    const uint32_t bdst = (uint32_t)(OFF_B + arow * 144 + akc0 * 16);

    auto produce = [&](int ci, uint32_t buf) {
        #pragma unroll
        for (int j = 0; j < 4; j++) {
            cp16(buf + adst + j * 16u, asrc + ci * 32 + j * 4);
            cp16(buf + bdst + j * 16u, bsrc + ci * 32 + j * 4);
        }
    };

    float acc[4][4][4];
    #pragma unroll
    for (int i = 0; i < 4; i++)
        #pragma unroll
        for (int j = 0; j < 4; j++)
            #pragma unroll
            for (int e = 0; e < 4; e++) acc[i][j][e] = 0.f;

    const uint32_t a_off = (uint32_t)((warp_m * 64 + (lid & 15)) * 144 + (lid & 16));
    const uint32_t b_off = (uint32_t)(OFF_B +
        (warp_n * 32 + (lid & 7) + ((lid & 16) >> 1)) * 144 + ((lid & 8) << 1));

    produce(0, sbase);             CP_COMMIT();
    produce(1, sbase + BUFSZ);     CP_COMMIT();

    int st = 0;
    for (int c = 0; c < 12; c++) {
        CP_WAIT1();
        __syncthreads();
        if (c + 2 < 12) {
            int s2 = st + 2; if (s2 >= 3) s2 -= 3;
            produce(c + 2, sbase + (uint32_t)s2 * BUFSZ);
        }
        CP_COMMIT();

        const uint32_t buf = sbase + (uint32_t)st * BUFSZ;
        #pragma unroll
        for (int s = 0; s < 4; s++) {       // 4 k8-steps per 32-ch chunk
            uint32_t af[4][4], bf[2][4];
            #pragma unroll
            for (int mf = 0; mf < 4; mf++)
                ldsm_x4(af[mf], buf + a_off + (uint32_t)(mf * 16 * 144) + s * 32u);
            #pragma unroll
            for (int np = 0; np < 2; np++)
                ldsm_x4(bf[np], buf + b_off + (uint32_t)(np * 16 * 144) + s * 32u);
            #pragma unroll
            for (int mf = 0; mf < 4; mf++)
                #pragma unroll
                for (int nf = 0; nf < 4; nf++)
                    mma_tf32(acc[mf][nf], af[mf], &bf[nf >> 1][(nf & 1) * 2]);
        }
        st += 1; if (st >= 3) st -= 3;
    }

    // ---- epilogue: BN + exact GELU ----
    #pragma unroll
    for (int mf = 0; mf < 4; mf++) {
        const int ml = warp_m * 64 + mf * 16 + (lid >> 2);
        #pragma unroll
        for (int half = 0; half < 2; half++) {
            int g = g0 + ml + half * 8;
            int bb = g / HW, p = g - bb * HW;
            float* orow = out + ((size_t)bb * CO + o0) * HW + p;
            #pragma unroll
            for (int nf = 0; nf < 4; nf++) {
                #pragma unroll
                for (int e = 0; e < 2; e++) {
                    int n = warp_n * 32 + nf * 8 + (lid & 3) * 2 + e;
                    float y = acc[mf][nf][half * 2 + e] * scp[n] + shp[n];
                    y = 0.5f * y * (1.0f + erff(y * 0.70710678118654752f));
                    orow[(size_t)n * HW] = y;
                }
            }
        }
    }
}

extern "C" void kernel_launch(void* const* d_in, const int* in_sizes, int n_in,
                              void* d_out, int out_size) {
    const float* x     = (const float*)d_in[0];
    const float* Wc    = (const float*)d_in[1];
    const float* bconv = (const float*)d_in[2];
    const float* gamma = (const float*)d_in[3];
    const float* beta  = (const float*)d_in[4];
    const float* rmean = (const float*)d_in[5];
    const float* rvar  = (const float*)d_in[6];
    float* out = (float*)d_out;

    passA_kernel<<<B_ * C_, 256>>>(x);
    cudaFuncSetAttribute(passB_kernel,
                         cudaFuncAttributeMaxDynamicSharedMemorySize, 32 * 385 * 4);
    dim3 gB(HW / 32, B_);   // (98, 32)
    passB_kernel<<<gB, 256, 32 * 385 * 4>>>(x);
    wconv_kernel<<<(CO * K2 + 255) / 256, 256>>>(Wc);

    cudaFuncSetAttribute(gemm_tf32_kernel,
                         cudaFuncAttributeMaxDynamicSharedMemorySize, SMEM_TOTAL);
    dim3 grid(CO / 128, HW * B_ / 128);   // (3, 784)
    gemm_tf32_kernel<<<grid, 256, SMEM_TOTAL>>>(bconv, gamma, beta, rmean, rvar, out);
}